// round 1
// baseline (speedup 1.0000x reference)
#include <cuda_runtime.h>
#include <math.h>
#include <float.h>

#define BB 2
#define SS 2048
#define DIM 4096
#define NH 32
#define NKV 8
#define HD 128
#define NREP 4
#define M_TOK (BB*SS)
#define KVDIM (NKV*HD)

// Scratch (allocation-free: device globals)
__device__ float g_xq[(size_t)M_TOK * DIM];     // [B,S,NH,HD]
__device__ float g_xk[(size_t)M_TOK * KVDIM];   // [B,S,NKV,HD]
__device__ float g_xv[(size_t)M_TOK * KVDIM];
__device__ float g_attn[(size_t)M_TOK * DIM];   // [B,S,NH,HD]

// ---------------------------------------------------------------------------
// SGEMM: C[m][n] = sum_k A[m*K+k] * Bm[n*K+k]   (both K-major, NT gemm)
// 128x128 tile, BK=16, 256 threads, 8x8 microtile.
// ---------------------------------------------------------------------------
__global__ __launch_bounds__(256) void sgemm_nt(
    const float* __restrict__ A, const float* __restrict__ Bm,
    float* __restrict__ C, int M, int N, int K)
{
    const int BM = 128, BN = 128, BK = 16;
    __shared__ float As[BK][BM + 4];
    __shared__ float Bs[BK][BN + 4];

    int tid = threadIdx.x;
    int tx = tid & 15, ty = tid >> 4;
    int m0 = blockIdx.y * BM, n0 = blockIdx.x * BN;

    float acc[8][8];
#pragma unroll
    for (int i = 0; i < 8; i++)
#pragma unroll
        for (int j = 0; j < 8; j++) acc[i][j] = 0.f;

    for (int k0 = 0; k0 < K; k0 += BK) {
#pragma unroll
        for (int r = 0; r < 2; r++) {
            int f = tid * 2 + r;             // 0..511
            int row = f >> 2;                // 0..127
            int kg  = (f & 3) * 4;           // 0,4,8,12
            float4 a = *(const float4*)&A[(size_t)(m0 + row) * K + k0 + kg];
            As[kg + 0][row] = a.x; As[kg + 1][row] = a.y;
            As[kg + 2][row] = a.z; As[kg + 3][row] = a.w;
            float4 b = *(const float4*)&Bm[(size_t)(n0 + row) * K + k0 + kg];
            Bs[kg + 0][row] = b.x; Bs[kg + 1][row] = b.y;
            Bs[kg + 2][row] = b.z; Bs[kg + 3][row] = b.w;
        }
        __syncthreads();
#pragma unroll
        for (int k = 0; k < BK; k++) {
            float a[8], b[8];
#pragma unroll
            for (int i = 0; i < 8; i++) a[i] = As[k][ty * 8 + i];
#pragma unroll
            for (int j = 0; j < 8; j++) b[j] = Bs[k][tx * 8 + j];
#pragma unroll
            for (int i = 0; i < 8; i++)
#pragma unroll
                for (int j = 0; j < 8; j++) acc[i][j] += a[i] * b[j];
        }
        __syncthreads();
    }

#pragma unroll
    for (int i = 0; i < 8; i++) {
        int m = m0 + ty * 8 + i;
#pragma unroll
        for (int j = 0; j < 8; j += 4) {
            float4 o = make_float4(acc[i][j], acc[i][j + 1], acc[i][j + 2], acc[i][j + 3]);
            *(float4*)&C[(size_t)m * N + n0 + tx * 8 + j] = o;
        }
    }
}

// ---------------------------------------------------------------------------
// RoPE in-place on t laid out [B,S,n_heads,HD]; pairs (2p, 2p+1)
// ---------------------------------------------------------------------------
__global__ void rope_kernel(float* __restrict__ t,
                            const float* __restrict__ fc,
                            const float* __restrict__ fs,
                            int n_heads, int total)
{
    int idx = blockIdx.x * blockDim.x + threadIdx.x;
    if (idx >= total) return;
    int p  = idx & 63;                 // HD/2 = 64
    int h  = (idx >> 6) % n_heads;
    int bs = (idx >> 6) / n_heads;     // b*S + s
    int srow = bs % SS;
    size_t off = ((size_t)bs * n_heads + h) * HD + 2 * p;
    float c  = fc[srow * 64 + p];
    float sn = fs[srow * 64 + p];
    float tr = t[off], ti = t[off + 1];
    t[off]     = tr * c - ti * sn;
    t[off + 1] = tr * sn + ti * c;
}

// ---------------------------------------------------------------------------
// Flash attention, fp32, causal, GQA (NREP=4).
// Block: 64 query rows x full head. BLOCK_N = 64. 256 threads (16x16).
// ---------------------------------------------------------------------------
#define FA_BM 64
#define FA_BN 64

struct AttnSmem {
    float q [FA_BM][HD + 4];
    float kT[HD]  [FA_BN + 4];
    float v [FA_BN][HD + 4];
    float s [FA_BM][FA_BN + 4];
    float row_m[FA_BM];
    float row_l[FA_BM];
    float row_a[FA_BM];
};

__global__ __launch_bounds__(256) void flash_attn(
    const float* __restrict__ xq, const float* __restrict__ xk,
    const float* __restrict__ xv, float* __restrict__ out)
{
    extern __shared__ char smem_raw[];
    AttnSmem* sm = (AttnSmem*)smem_raw;

    int tid = threadIdx.x;
    int tx = tid & 15, ty = tid >> 4;
    int qt = blockIdx.x;
    int bh = blockIdx.y;
    int b = bh / NH, h = bh % NH, kvh = h / NREP;
    int q0 = qt * FA_BM;
    const float scale = 0.08838834764831845f;   // 1/sqrt(128)

    // load Q tile (64x128): 8 float4 per thread
#pragma unroll
    for (int i = 0; i < 8; i++) {
        int f4 = tid + i * 256;
        int row = f4 >> 5;
        int c4  = (f4 & 31) * 4;
        float4 qa = *(const float4*)&xq[((size_t)(b * SS + q0 + row) * NH + h) * HD + c4];
        *(float4*)&sm->q[row][c4] = qa;
    }
    if (tid < FA_BM) { sm->row_m[tid] = -FLT_MAX; sm->row_l[tid] = 0.f; }

    float o[4][8];
#pragma unroll
    for (int i = 0; i < 4; i++)
#pragma unroll
        for (int j = 0; j < 8; j++) o[i][j] = 0.f;

    for (int nt = 0; nt <= qt; nt++) {
        int k0 = nt * FA_BN;
        __syncthreads();   // protects q on first iter, s/v/kT reuse afterwards

        // load K (transposed) and V tiles
#pragma unroll
        for (int i = 0; i < 8; i++) {
            int f4 = tid + i * 256;
            int row = f4 >> 5;
            int c4  = (f4 & 31) * 4;
            size_t goff = ((size_t)(b * SS + k0 + row) * NKV + kvh) * HD + c4;
            float4 ka = *(const float4*)&xk[goff];
            sm->kT[c4 + 0][row] = ka.x; sm->kT[c4 + 1][row] = ka.y;
            sm->kT[c4 + 2][row] = ka.z; sm->kT[c4 + 3][row] = ka.w;
            float4 va = *(const float4*)&xv[goff];
            *(float4*)&sm->v[row][c4] = va;
        }
        __syncthreads();

        // scores: each thread computes 4x4
        float acc[4][4];
#pragma unroll
        for (int i = 0; i < 4; i++)
#pragma unroll
            for (int j = 0; j < 4; j++) acc[i][j] = 0.f;

#pragma unroll 8
        for (int d = 0; d < HD; d++) {
            float a[4], bb[4];
#pragma unroll
            for (int i = 0; i < 4; i++) a[i]  = sm->q [ty * 4 + i][d];
#pragma unroll
            for (int j = 0; j < 4; j++) bb[j] = sm->kT[d][tx * 4 + j];
#pragma unroll
            for (int i = 0; i < 4; i++)
#pragma unroll
                for (int j = 0; j < 4; j++) acc[i][j] += a[i] * bb[j];
        }
#pragma unroll
        for (int i = 0; i < 4; i++) {
#pragma unroll
            for (int j = 0; j < 4; j++) {
                int gi = q0 + ty * 4 + i;
                int gj = k0 + tx * 4 + j;
                float val = acc[i][j] * scale;
                if (gj > gi) val = -FLT_MAX;
                sm->s[ty * 4 + i][tx * 4 + j] = val;
            }
        }
        __syncthreads();

        // online softmax: one thread per row
        if (tid < FA_BM) {
            int r = tid;
            float mold = sm->row_m[r];
            float mx = mold;
#pragma unroll 8
            for (int j = 0; j < FA_BN; j++) mx = fmaxf(mx, sm->s[r][j]);
            float alpha = expf(mold - mx);
            float sum = 0.f;
#pragma unroll 8
            for (int j = 0; j < FA_BN; j++) {
                float p = expf(sm->s[r][j] - mx);
                sm->s[r][j] = p;
                sum += p;
            }
            sm->row_m[r] = mx;
            sm->row_l[r] = sm->row_l[r] * alpha + sum;
            sm->row_a[r] = alpha;
        }
        __syncthreads();

        // O update: o = o*alpha + P@V ; thread owns rows ty*4..+3, cols tx*8..+7
        float al[4];
#pragma unroll
        for (int i = 0; i < 4; i++) al[i] = sm->row_a[ty * 4 + i];
#pragma unroll
        for (int i = 0; i < 4; i++)
#pragma unroll
            for (int c = 0; c < 8; c++) o[i][c] *= al[i];

#pragma unroll 4
        for (int j = 0; j < FA_BN; j++) {
            float p[4];
#pragma unroll
            for (int i = 0; i < 4; i++) p[i] = sm->s[ty * 4 + i][j];
            float4 v0 = *(const float4*)&sm->v[j][tx * 8];
            float4 v1 = *(const float4*)&sm->v[j][tx * 8 + 4];
            float vv[8] = {v0.x, v0.y, v0.z, v0.w, v1.x, v1.y, v1.z, v1.w};
#pragma unroll
            for (int i = 0; i < 4; i++)
#pragma unroll
                for (int c = 0; c < 8; c++) o[i][c] += p[i] * vv[c];
        }
    }

    // finalize: divide by l, write out [B,S,NH,HD]
    float linv[4];
#pragma unroll
    for (int i = 0; i < 4; i++) linv[i] = 1.f / sm->row_l[ty * 4 + i];
#pragma unroll
    for (int i = 0; i < 4; i++) {
        int row = q0 + ty * 4 + i;
        size_t base = ((size_t)(b * SS + row) * NH + h) * HD + tx * 8;
        float4 o0 = make_float4(o[i][0] * linv[i], o[i][1] * linv[i],
                                o[i][2] * linv[i], o[i][3] * linv[i]);
        float4 o1 = make_float4(o[i][4] * linv[i], o[i][5] * linv[i],
                                o[i][6] * linv[i], o[i][7] * linv[i]);
        *(float4*)&out[base]     = o0;
        *(float4*)&out[base + 4] = o1;
    }
}

// ---------------------------------------------------------------------------
extern "C" void kernel_launch(void* const* d_in, const int* in_sizes, int n_in,
                              void* d_out, int out_size)
{
    const float* x   = (const float*)d_in[0];
    const float* wq  = (const float*)d_in[1];
    const float* wk  = (const float*)d_in[2];
    const float* wv  = (const float*)d_in[3];
    const float* wo  = (const float*)d_in[4];
    const float* fc  = (const float*)d_in[5];
    const float* fs  = (const float*)d_in[6];
    // d_in[7] = mask (unused; causal mask applied analytically)
    float* out = (float*)d_out;

    float* xq = nullptr; cudaGetSymbolAddress((void**)&xq, g_xq);
    float* xk = nullptr; cudaGetSymbolAddress((void**)&xk, g_xk);
    float* xv = nullptr; cudaGetSymbolAddress((void**)&xv, g_xv);
    float* at = nullptr; cudaGetSymbolAddress((void**)&at, g_attn);

    cudaFuncSetAttribute(flash_attn, cudaFuncAttributeMaxDynamicSharedMemorySize,
                         (int)sizeof(AttnSmem));

    // Q/K/V projections
    dim3 gq(DIM / 128, M_TOK / 128);
    sgemm_nt<<<gq, 256>>>(x, wq, xq, M_TOK, DIM, DIM);
    dim3 gkv(KVDIM / 128, M_TOK / 128);
    sgemm_nt<<<gkv, 256>>>(x, wk, xk, M_TOK, KVDIM, DIM);
    sgemm_nt<<<gkv, 256>>>(x, wv, xv, M_TOK, KVDIM, DIM);

    // RoPE
    int totq = BB * SS * NH  * (HD / 2);
    int totk = BB * SS * NKV * (HD / 2);
    rope_kernel<<<(totq + 255) / 256, 256>>>(xq, fc, fs, NH,  totq);
    rope_kernel<<<(totk + 255) / 256, 256>>>(xk, fc, fs, NKV, totk);

    // attention
    dim3 ga(SS / FA_BM, BB * NH);
    flash_attn<<<ga, 256, sizeof(AttnSmem)>>>(xq, xk, xv, at);

    // output projection
    sgemm_nt<<<gq, 256>>>(at, wo, out, M_TOK, DIM, DIM);
}

// round 4
// speedup vs baseline: 1.8910x; 1.8910x over previous
#include <cuda_runtime.h>
#include <cuda_bf16.h>
#include <cstdint>
#include <cstddef>
#include <math.h>
#include <float.h>

typedef unsigned int u32;

#define BB 2
#define SS 2048
#define DIM 4096
#define NH 32
#define NKV 8
#define HD 128
#define NREP 4
#define M_TOK (BB*SS)
#define KVDIM (NKV*HD)

// ---------------- scratch (allocation-free device globals) ----------------
__device__ float g_xq[(size_t)M_TOK * DIM];
__device__ float g_xk[(size_t)M_TOK * KVDIM];
__device__ float g_xv[(size_t)M_TOK * KVDIM];
__device__ float g_attn[(size_t)M_TOK * DIM];

__device__ __nv_bfloat16 g_xh[(size_t)M_TOK * DIM],  g_xl[(size_t)M_TOK * DIM];
__device__ __nv_bfloat16 g_wqh[(size_t)DIM * DIM],   g_wql[(size_t)DIM * DIM];
__device__ __nv_bfloat16 g_wkh[(size_t)KVDIM * DIM], g_wkl[(size_t)KVDIM * DIM];
__device__ __nv_bfloat16 g_wvh[(size_t)KVDIM * DIM], g_wvl[(size_t)KVDIM * DIM];
__device__ __nv_bfloat16 g_woh[(size_t)DIM * DIM],   g_wol[(size_t)DIM * DIM];
__device__ __nv_bfloat16 g_ah[(size_t)M_TOK * DIM],  g_al[(size_t)M_TOK * DIM];

// ---------------------------------------------------------------------------
// split fp32 -> (bf16 hi, bf16 lo)
// ---------------------------------------------------------------------------
__global__ void split_kernel(const float* __restrict__ in,
                             __nv_bfloat16* __restrict__ hi,
                             __nv_bfloat16* __restrict__ lo, int n)
{
    int i = (blockIdx.x * blockDim.x + threadIdx.x) * 4;
    if (i >= n) return;
    float4 v = *(const float4*)&in[i];
    float f[4] = {v.x, v.y, v.z, v.w};
    __nv_bfloat16 h[4], l[4];
#pragma unroll
    for (int k = 0; k < 4; k++) {
        h[k] = __float2bfloat16_rn(f[k]);
        l[k] = __float2bfloat16_rn(f[k] - __bfloat162float(h[k]));
    }
    *(__nv_bfloat162*)&hi[i]     = __nv_bfloat162(h[0], h[1]);
    *(__nv_bfloat162*)&hi[i + 2] = __nv_bfloat162(h[2], h[3]);
    *(__nv_bfloat162*)&lo[i]     = __nv_bfloat162(l[0], l[1]);
    *(__nv_bfloat162*)&lo[i + 2] = __nv_bfloat162(l[2], l[3]);
}

// ---------------------------------------------------------------------------
// bf16x2 split GEMM (NT): C[m][n] = sum_k A[m][k]*B[n][k], fp32 out.
// Computes Ah*Bh + Ah*Bl + Al*Bh on the tensor pipe.
// Block tile 128x128x32, 8 warps (2x4), warp tile 64x32, mma.m16n8k16.
// ---------------------------------------------------------------------------
#define GSTR 40      // smem row stride in bf16 (80B) -> conflict-free ldmatrix
#define GTILE (128*GSTR)

__device__ __forceinline__ void cpasync16(const void* s, const void* g) {
    u32 sa = (u32)__cvta_generic_to_shared(s);
    asm volatile("cp.async.cg.shared.global [%0], [%1], 16;\n" :: "r"(sa), "l"(g));
}
__device__ __forceinline__ void ldsm4(u32& r0, u32& r1, u32& r2,
                                      u32& r3, const __nv_bfloat16* p) {
    u32 a = (u32)__cvta_generic_to_shared(p);
    asm volatile("ldmatrix.sync.aligned.m8n8.x4.shared.b16 {%0,%1,%2,%3}, [%4];"
                 : "=r"(r0), "=r"(r1), "=r"(r2), "=r"(r3) : "r"(a));
}
__device__ __forceinline__ void mma16816(float* c, const u32* a, const u32* b) {
    asm volatile(
        "mma.sync.aligned.m16n8k16.row.col.f32.bf16.bf16.f32 "
        "{%0,%1,%2,%3}, {%4,%5,%6,%7}, {%8,%9}, {%0,%1,%2,%3};"
        : "+f"(c[0]), "+f"(c[1]), "+f"(c[2]), "+f"(c[3])
        : "r"(a[0]), "r"(a[1]), "r"(a[2]), "r"(a[3]), "r"(b[0]), "r"(b[1]));
}

__device__ __forceinline__ void load_stage(
    __nv_bfloat16* sb,
    const __nv_bfloat16* __restrict__ Ah, const __nv_bfloat16* __restrict__ Al,
    const __nv_bfloat16* __restrict__ Bh, const __nv_bfloat16* __restrict__ Bl,
    int tid, int m0, int n0, int K, int k0)
{
#pragma unroll
    for (int i = 0; i < 2; i++) {
        int c = tid + i * 256;
        int row = c >> 2;
        int col = (c & 3) * 8;
        size_t ga = (size_t)(m0 + row) * K + k0 + col;
        size_t gb = (size_t)(n0 + row) * K + k0 + col;
        cpasync16(&sb[0 * GTILE + row * GSTR + col], &Ah[ga]);
        cpasync16(&sb[1 * GTILE + row * GSTR + col], &Al[ga]);
        cpasync16(&sb[2 * GTILE + row * GSTR + col], &Bh[gb]);
        cpasync16(&sb[3 * GTILE + row * GSTR + col], &Bl[gb]);
    }
    asm volatile("cp.async.commit_group;");
}

__global__ __launch_bounds__(256, 1) void gemm_bf16x2(
    const __nv_bfloat16* __restrict__ Ah, const __nv_bfloat16* __restrict__ Al,
    const __nv_bfloat16* __restrict__ Bh, const __nv_bfloat16* __restrict__ Bl,
    float* __restrict__ C, int M, int N, int K)
{
    extern __shared__ __nv_bfloat16 smem[];
    int tid = threadIdx.x;
    int lane = tid & 31, wid = tid >> 5;
    int wm = wid & 1, wn = wid >> 1;           // warp tile: rows wm*64, cols wn*32
    int m0 = blockIdx.y * 128, n0 = blockIdx.x * 128;

    float acc[4][4][4];
#pragma unroll
    for (int i = 0; i < 4; i++)
#pragma unroll
        for (int j = 0; j < 4; j++)
#pragma unroll
            for (int k = 0; k < 4; k++) acc[i][j][k] = 0.f;

    const int KT = K / 32;

    load_stage(smem, Ah, Al, Bh, Bl, tid, m0, n0, K, 0);
    asm volatile("cp.async.wait_group 0;");
    __syncthreads();

    for (int kt = 0; kt < KT; kt++) {
        int cur = kt & 1;
        if (kt + 1 < KT)
            load_stage(smem + (cur ^ 1) * 4 * GTILE, Ah, Al, Bh, Bl,
                       tid, m0, n0, K, (kt + 1) * 32);

        const __nv_bfloat16* sAh = smem + cur * 4 * GTILE;
        const __nv_bfloat16* sAl = sAh + GTILE;
        const __nv_bfloat16* sBh = sAh + 2 * GTILE;
        const __nv_bfloat16* sBl = sAh + 3 * GTILE;

#pragma unroll
        for (int kk = 0; kk < 32; kk += 16) {
            u32 ah[4][4], al[4][4], bh[4][2], bl[4][2];
            int arow = wm * 64 + (lane & 7) + ((lane >> 3) & 1) * 8;
            int acol = kk + ((lane >> 4) & 1) * 8;
#pragma unroll
            for (int mt = 0; mt < 4; mt++) {
                const __nv_bfloat16* pa = sAh + (arow + mt * 16) * GSTR + acol;
                ldsm4(ah[mt][0], ah[mt][1], ah[mt][2], ah[mt][3], pa);
                const __nv_bfloat16* pl = sAl + (arow + mt * 16) * GSTR + acol;
                ldsm4(al[mt][0], al[mt][1], al[mt][2], al[mt][3], pl);
            }
            int brow = wn * 32 + (lane & 7) + ((lane >> 4) & 1) * 8;
            int bcol = kk + ((lane >> 3) & 1) * 8;
#pragma unroll
            for (int p = 0; p < 2; p++) {
                u32 r0, r1, r2, r3;
                ldsm4(r0, r1, r2, r3, sBh + (brow + p * 16) * GSTR + bcol);
                bh[2 * p][0] = r0; bh[2 * p][1] = r1;
                bh[2 * p + 1][0] = r2; bh[2 * p + 1][1] = r3;
                ldsm4(r0, r1, r2, r3, sBl + (brow + p * 16) * GSTR + bcol);
                bl[2 * p][0] = r0; bl[2 * p][1] = r1;
                bl[2 * p + 1][0] = r2; bl[2 * p + 1][1] = r3;
            }
#pragma unroll
            for (int mt = 0; mt < 4; mt++) {
#pragma unroll
                for (int nt = 0; nt < 4; nt++) {
                    mma16816(acc[mt][nt], ah[mt], bh[nt]);
                    mma16816(acc[mt][nt], ah[mt], bl[nt]);
                    mma16816(acc[mt][nt], al[mt], bh[nt]);
                }
            }
        }
        asm volatile("cp.async.wait_group 0;");
        __syncthreads();
    }

    // epilogue
#pragma unroll
    for (int mt = 0; mt < 4; mt++) {
#pragma unroll
        for (int nt = 0; nt < 4; nt++) {
            int r = m0 + wm * 64 + mt * 16 + (lane >> 2);
            int c = n0 + wn * 32 + nt * 8 + (lane & 3) * 2;
            float2 v0 = make_float2(acc[mt][nt][0], acc[mt][nt][1]);
            float2 v1 = make_float2(acc[mt][nt][2], acc[mt][nt][3]);
            *(float2*)&C[(size_t)r * N + c] = v0;
            *(float2*)&C[(size_t)(r + 8) * N + c] = v1;
        }
    }
}

// ---------------------------------------------------------------------------
// RoPE in-place on t laid out [B,S,n_heads,HD]
// ---------------------------------------------------------------------------
__global__ void rope_kernel(float* __restrict__ t,
                            const float* __restrict__ fc,
                            const float* __restrict__ fs,
                            int n_heads, int total)
{
    int idx = blockIdx.x * blockDim.x + threadIdx.x;
    if (idx >= total) return;
    int p  = idx & 63;
    int h  = (idx >> 6) % n_heads;
    int bs = (idx >> 6) / n_heads;
    int srow = bs % SS;
    size_t off = ((size_t)bs * n_heads + h) * HD + 2 * p;
    float c  = fc[srow * 64 + p];
    float sn = fs[srow * 64 + p];
    float tr = t[off], ti = t[off + 1];
    t[off]     = tr * c - ti * sn;
    t[off + 1] = tr * sn + ti * c;
}

// ---------------------------------------------------------------------------
// Flash attention, fp32, causal, GQA. 64x64 tiles, 256 threads (16x16),
// warp-shuffle online softmax.
// ---------------------------------------------------------------------------
#define FA_BM 64
#define FA_BN 64

struct AttnSmem {
    float q [FA_BM][HD + 4];
    float kT[HD]  [FA_BN + 4];
    float v [FA_BN][HD + 4];
    float s [FA_BM][FA_BN + 4];
};

__global__ __launch_bounds__(256) void flash_attn(
    const float* __restrict__ xq, const float* __restrict__ xk,
    const float* __restrict__ xv, float* __restrict__ out)
{
    extern __shared__ char smem_raw[];
    AttnSmem* sm = (AttnSmem*)smem_raw;

    int tid = threadIdx.x;
    int tx = tid & 15, ty = tid >> 4;
    int qt = blockIdx.x;
    int bh = blockIdx.y;
    int b = bh / NH, h = bh % NH, kvh = h / NREP;
    int q0 = qt * FA_BM;
    const float scale = 0.08838834764831845f;

#pragma unroll
    for (int i = 0; i < 8; i++) {
        int f4 = tid + i * 256;
        int row = f4 >> 5;
        int c4  = (f4 & 31) * 4;
        float4 qa = *(const float4*)&xq[((size_t)(b * SS + q0 + row) * NH + h) * HD + c4];
        *(float4*)&sm->q[row][c4] = qa;
    }

    float row_m[4], row_l[4];
#pragma unroll
    for (int i = 0; i < 4; i++) { row_m[i] = -FLT_MAX; row_l[i] = 0.f; }

    float o[4][8];
#pragma unroll
    for (int i = 0; i < 4; i++)
#pragma unroll
        for (int j = 0; j < 8; j++) o[i][j] = 0.f;

    for (int nt = 0; nt <= qt; nt++) {
        int k0 = nt * FA_BN;
        __syncthreads();
#pragma unroll
        for (int i = 0; i < 8; i++) {
            int f4 = tid + i * 256;
            int row = f4 >> 5;
            int c4  = (f4 & 31) * 4;
            size_t goff = ((size_t)(b * SS + k0 + row) * NKV + kvh) * HD + c4;
            float4 ka = *(const float4*)&xk[goff];
            sm->kT[c4 + 0][row] = ka.x; sm->kT[c4 + 1][row] = ka.y;
            sm->kT[c4 + 2][row] = ka.z; sm->kT[c4 + 3][row] = ka.w;
            float4 va = *(const float4*)&xv[goff];
            *(float4*)&sm->v[row][c4] = va;
        }
        __syncthreads();

        float acc[4][4];
#pragma unroll
        for (int i = 0; i < 4; i++)
#pragma unroll
            for (int j = 0; j < 4; j++) acc[i][j] = 0.f;

#pragma unroll 8
        for (int d = 0; d < HD; d++) {
            float a[4], bb[4];
#pragma unroll
            for (int i = 0; i < 4; i++) a[i]  = sm->q [ty * 4 + i][d];
#pragma unroll
            for (int j = 0; j < 4; j++) bb[j] = sm->kT[d][tx * 4 + j];
#pragma unroll
            for (int i = 0; i < 4; i++)
#pragma unroll
                for (int j = 0; j < 4; j++) acc[i][j] += a[i] * bb[j];
        }

        // scale + causal mask
#pragma unroll
        for (int i = 0; i < 4; i++) {
            int gi = q0 + ty * 4 + i;
#pragma unroll
            for (int j = 0; j < 4; j++) {
                int gj = k0 + tx * 4 + j;
                acc[i][j] = (gj > gi) ? -FLT_MAX : acc[i][j] * scale;
            }
        }

        // warp-shuffle online softmax (rows reduced across the 16 tx threads)
#pragma unroll
        for (int i = 0; i < 4; i++) {
            float m = fmaxf(fmaxf(acc[i][0], acc[i][1]), fmaxf(acc[i][2], acc[i][3]));
#pragma unroll
            for (int off = 1; off < 16; off <<= 1)
                m = fmaxf(m, __shfl_xor_sync(0xffffffffu, m, off));
            float newm = fmaxf(row_m[i], m);
            float alpha = __expf(row_m[i] - newm);
            float s = 0.f;
#pragma unroll
            for (int j = 0; j < 4; j++) {
                float p = __expf(acc[i][j] - newm);
                sm->s[ty * 4 + i][tx * 4 + j] = p;
                s += p;
            }
#pragma unroll
            for (int off = 1; off < 16; off <<= 1)
                s += __shfl_xor_sync(0xffffffffu, s, off);
            row_l[i] = row_l[i] * alpha + s;
            row_m[i] = newm;
#pragma unroll
            for (int c = 0; c < 8; c++) o[i][c] *= alpha;
        }
        __syncthreads();

        // O += P @ V
#pragma unroll 4
        for (int j = 0; j < FA_BN; j++) {
            float p[4];
#pragma unroll
            for (int i = 0; i < 4; i++) p[i] = sm->s[ty * 4 + i][j];
            float4 v0 = *(const float4*)&sm->v[j][tx * 8];
            float4 v1 = *(const float4*)&sm->v[j][tx * 8 + 4];
            float vv[8] = {v0.x, v0.y, v0.z, v0.w, v1.x, v1.y, v1.z, v1.w};
#pragma unroll
            for (int i = 0; i < 4; i++)
#pragma unroll
                for (int c = 0; c < 8; c++) o[i][c] += p[i] * vv[c];
        }
    }

#pragma unroll
    for (int i = 0; i < 4; i++) {
        float linv = 1.f / row_l[i];
        int row = q0 + ty * 4 + i;
        size_t base = ((size_t)(b * SS + row) * NH + h) * HD + tx * 8;
        float4 o0 = make_float4(o[i][0] * linv, o[i][1] * linv, o[i][2] * linv, o[i][3] * linv);
        float4 o1 = make_float4(o[i][4] * linv, o[i][5] * linv, o[i][6] * linv, o[i][7] * linv);
        *(float4*)&out[base]     = o0;
        *(float4*)&out[base + 4] = o1;
    }
}

// ---------------------------------------------------------------------------
extern "C" void kernel_launch(void* const* d_in, const int* in_sizes, int n_in,
                              void* d_out, int out_size)
{
    const float* x   = (const float*)d_in[0];
    const float* wq  = (const float*)d_in[1];
    const float* wk  = (const float*)d_in[2];
    const float* wv  = (const float*)d_in[3];
    const float* wo  = (const float*)d_in[4];
    const float* fc  = (const float*)d_in[5];
    const float* fs  = (const float*)d_in[6];
    float* out = (float*)d_out;

    float *xq, *xk, *xv, *at;
    cudaGetSymbolAddress((void**)&xq, g_xq);
    cudaGetSymbolAddress((void**)&xk, g_xk);
    cudaGetSymbolAddress((void**)&xv, g_xv);
    cudaGetSymbolAddress((void**)&at, g_attn);
    __nv_bfloat16 *xh, *xl, *wqh, *wql, *wkh, *wkl, *wvh, *wvl, *woh, *wol, *ah, *al;
    cudaGetSymbolAddress((void**)&xh, g_xh);   cudaGetSymbolAddress((void**)&xl, g_xl);
    cudaGetSymbolAddress((void**)&wqh, g_wqh); cudaGetSymbolAddress((void**)&wql, g_wql);
    cudaGetSymbolAddress((void**)&wkh, g_wkh); cudaGetSymbolAddress((void**)&wkl, g_wkl);
    cudaGetSymbolAddress((void**)&wvh, g_wvh); cudaGetSymbolAddress((void**)&wvl, g_wvl);
    cudaGetSymbolAddress((void**)&woh, g_woh); cudaGetSymbolAddress((void**)&wol, g_wol);
    cudaGetSymbolAddress((void**)&ah, g_ah);   cudaGetSymbolAddress((void**)&al, g_al);

    const int GEMM_SMEM = 2 * 4 * GTILE * (int)sizeof(__nv_bfloat16);  // 81920
    cudaFuncSetAttribute(gemm_bf16x2, cudaFuncAttributeMaxDynamicSharedMemorySize, GEMM_SMEM);
    cudaFuncSetAttribute(flash_attn, cudaFuncAttributeMaxDynamicSharedMemorySize,
                         (int)sizeof(AttnSmem));

    // splits
    int nx  = M_TOK * DIM, nw = DIM * DIM, nkv = KVDIM * DIM;
    split_kernel<<<nx / 4 / 256, 256>>>(x, xh, xl, nx);
    split_kernel<<<nw / 4 / 256, 256>>>(wq, wqh, wql, nw);
    split_kernel<<<nkv / 4 / 256, 256>>>(wk, wkh, wkl, nkv);
    split_kernel<<<nkv / 4 / 256, 256>>>(wv, wvh, wvl, nkv);
    split_kernel<<<nw / 4 / 256, 256>>>(wo, woh, wol, nw);

    // projections on tensor pipe
    dim3 gq(DIM / 128, M_TOK / 128);
    dim3 gkv(KVDIM / 128, M_TOK / 128);
    gemm_bf16x2<<<gq, 256, GEMM_SMEM>>>(xh, xl, wqh, wql, xq, M_TOK, DIM, DIM);
    gemm_bf16x2<<<gkv, 256, GEMM_SMEM>>>(xh, xl, wkh, wkl, xk, M_TOK, KVDIM, DIM);
    gemm_bf16x2<<<gkv, 256, GEMM_SMEM>>>(xh, xl, wvh, wvl, xv, M_TOK, KVDIM, DIM);

    // RoPE
    int totq = BB * SS * NH  * (HD / 2);
    int totk = BB * SS * NKV * (HD / 2);
    rope_kernel<<<(totq + 255) / 256, 256>>>(xq, fc, fs, NH,  totq);
    rope_kernel<<<(totk + 255) / 256, 256>>>(xk, fc, fs, NKV, totk);

    // attention (fp32)
    dim3 ga(SS / FA_BM, BB * NH);
    flash_attn<<<ga, 256, sizeof(AttnSmem)>>>(xq, xk, xv, at);

    // output projection
    split_kernel<<<nx / 4 / 256, 256>>>(at, ah, al, nx);
    gemm_bf16x2<<<gq, 256, GEMM_SMEM>>>(ah, al, woh, wol, out, M_TOK, DIM, DIM);
}

// round 5
// speedup vs baseline: 2.9615x; 1.5660x over previous
#include <cuda_runtime.h>
#include <cuda_bf16.h>
#include <cuda_fp16.h>
#include <cstdint>
#include <cstddef>
#include <math.h>
#include <float.h>

typedef unsigned int u32;

#define BB 2
#define SS 2048
#define DIM 4096
#define NH 32
#define NKV 8
#define HD 128
#define NREP 4
#define M_TOK (BB*SS)
#define KVDIM (NKV*HD)

// ---------------- scratch (allocation-free device globals) ----------------
__device__ float g_xq[(size_t)M_TOK * DIM];
__device__ float g_xk[(size_t)M_TOK * KVDIM];
__device__ float g_xv[(size_t)M_TOK * KVDIM];
__device__ float g_attn[(size_t)M_TOK * DIM];

__device__ __nv_bfloat16 g_xh[(size_t)M_TOK * DIM],  g_xl[(size_t)M_TOK * DIM];
__device__ __nv_bfloat16 g_wqh[(size_t)DIM * DIM],   g_wql[(size_t)DIM * DIM];
__device__ __nv_bfloat16 g_wkh[(size_t)KVDIM * DIM], g_wkl[(size_t)KVDIM * DIM];
__device__ __nv_bfloat16 g_wvh[(size_t)KVDIM * DIM], g_wvl[(size_t)KVDIM * DIM];
__device__ __nv_bfloat16 g_woh[(size_t)DIM * DIM],   g_wol[(size_t)DIM * DIM];
__device__ __nv_bfloat16 g_ah[(size_t)M_TOK * DIM],  g_al[(size_t)M_TOK * DIM];

// fp16 attention operands
__device__ __half g_qh[(size_t)M_TOK * DIM],   g_ql[(size_t)M_TOK * DIM];
__device__ __half g_kh[(size_t)M_TOK * KVDIM], g_kl[(size_t)M_TOK * KVDIM];
__device__ __half g_vh[(size_t)M_TOK * KVDIM];

// ---------------------------------------------------------------------------
// split fp32 -> (bf16 hi, bf16 lo)
// ---------------------------------------------------------------------------
__global__ void split_kernel(const float* __restrict__ in,
                             __nv_bfloat16* __restrict__ hi,
                             __nv_bfloat16* __restrict__ lo, int n)
{
    int i = (blockIdx.x * blockDim.x + threadIdx.x) * 4;
    if (i >= n) return;
    float4 v = *(const float4*)&in[i];
    float f[4] = {v.x, v.y, v.z, v.w};
    __nv_bfloat16 h[4], l[4];
#pragma unroll
    for (int k = 0; k < 4; k++) {
        h[k] = __float2bfloat16_rn(f[k]);
        l[k] = __float2bfloat16_rn(f[k] - __bfloat162float(h[k]));
    }
    *(__nv_bfloat162*)&hi[i]     = __nv_bfloat162(h[0], h[1]);
    *(__nv_bfloat162*)&hi[i + 2] = __nv_bfloat162(h[2], h[3]);
    *(__nv_bfloat162*)&lo[i]     = __nv_bfloat162(l[0], l[1]);
    *(__nv_bfloat162*)&lo[i + 2] = __nv_bfloat162(l[2], l[3]);
}

// fp32 -> fp16 (single)
__global__ void split_half(const float* __restrict__ in, __half* __restrict__ out, int n)
{
    int i = (blockIdx.x * blockDim.x + threadIdx.x) * 4;
    if (i >= n) return;
    float4 v = *(const float4*)&in[i];
    *(__half2*)&out[i]     = __floats2half2_rn(v.x, v.y);
    *(__half2*)&out[i + 2] = __floats2half2_rn(v.z, v.w);
}

// ---------------------------------------------------------------------------
// bf16x2 split GEMM (NT), unchanged from round 4 (passing).
// ---------------------------------------------------------------------------
#define GSTR 40
#define GTILE (128*GSTR)

__device__ __forceinline__ void cpasync16(const void* s, const void* g) {
    u32 sa = (u32)__cvta_generic_to_shared(s);
    asm volatile("cp.async.cg.shared.global [%0], [%1], 16;\n" :: "r"(sa), "l"(g));
}
__device__ __forceinline__ void ldsm4(u32& r0, u32& r1, u32& r2,
                                      u32& r3, const void* p) {
    u32 a = (u32)__cvta_generic_to_shared(p);
    asm volatile("ldmatrix.sync.aligned.m8n8.x4.shared.b16 {%0,%1,%2,%3}, [%4];"
                 : "=r"(r0), "=r"(r1), "=r"(r2), "=r"(r3) : "r"(a));
}
__device__ __forceinline__ void ldsm4t(u32& r0, u32& r1, u32& r2,
                                       u32& r3, const void* p) {
    u32 a = (u32)__cvta_generic_to_shared(p);
    asm volatile("ldmatrix.sync.aligned.m8n8.x4.trans.shared.b16 {%0,%1,%2,%3}, [%4];"
                 : "=r"(r0), "=r"(r1), "=r"(r2), "=r"(r3) : "r"(a));
}
__device__ __forceinline__ void mma16816(float* c, const u32* a, const u32* b) {
    asm volatile(
        "mma.sync.aligned.m16n8k16.row.col.f32.bf16.bf16.f32 "
        "{%0,%1,%2,%3}, {%4,%5,%6,%7}, {%8,%9}, {%0,%1,%2,%3};"
        : "+f"(c[0]), "+f"(c[1]), "+f"(c[2]), "+f"(c[3])
        : "r"(a[0]), "r"(a[1]), "r"(a[2]), "r"(a[3]), "r"(b[0]), "r"(b[1]));
}
__device__ __forceinline__ void mma16816h(float* c, const u32* a, const u32* b) {
    asm volatile(
        "mma.sync.aligned.m16n8k16.row.col.f32.f16.f16.f32 "
        "{%0,%1,%2,%3}, {%4,%5,%6,%7}, {%8,%9}, {%0,%1,%2,%3};"
        : "+f"(c[0]), "+f"(c[1]), "+f"(c[2]), "+f"(c[3])
        : "r"(a[0]), "r"(a[1]), "r"(a[2]), "r"(a[3]), "r"(b[0]), "r"(b[1]));
}

__device__ __forceinline__ void load_stage(
    __nv_bfloat16* sb,
    const __nv_bfloat16* __restrict__ Ah, const __nv_bfloat16* __restrict__ Al,
    const __nv_bfloat16* __restrict__ Bh, const __nv_bfloat16* __restrict__ Bl,
    int tid, int m0, int n0, int K, int k0)
{
#pragma unroll
    for (int i = 0; i < 2; i++) {
        int c = tid + i * 256;
        int row = c >> 2;
        int col = (c & 3) * 8;
        size_t ga = (size_t)(m0 + row) * K + k0 + col;
        size_t gb = (size_t)(n0 + row) * K + k0 + col;
        cpasync16(&sb[0 * GTILE + row * GSTR + col], &Ah[ga]);
        cpasync16(&sb[1 * GTILE + row * GSTR + col], &Al[ga]);
        cpasync16(&sb[2 * GTILE + row * GSTR + col], &Bh[gb]);
        cpasync16(&sb[3 * GTILE + row * GSTR + col], &Bl[gb]);
    }
    asm volatile("cp.async.commit_group;");
}

__global__ __launch_bounds__(256, 1) void gemm_bf16x2(
    const __nv_bfloat16* __restrict__ Ah, const __nv_bfloat16* __restrict__ Al,
    const __nv_bfloat16* __restrict__ Bh, const __nv_bfloat16* __restrict__ Bl,
    float* __restrict__ C, int M, int N, int K)
{
    extern __shared__ __nv_bfloat16 smem[];
    int tid = threadIdx.x;
    int lane = tid & 31, wid = tid >> 5;
    int wm = wid & 1, wn = wid >> 1;
    int m0 = blockIdx.y * 128, n0 = blockIdx.x * 128;

    float acc[4][4][4];
#pragma unroll
    for (int i = 0; i < 4; i++)
#pragma unroll
        for (int j = 0; j < 4; j++)
#pragma unroll
            for (int k = 0; k < 4; k++) acc[i][j][k] = 0.f;

    const int KT = K / 32;

    load_stage(smem, Ah, Al, Bh, Bl, tid, m0, n0, K, 0);
    asm volatile("cp.async.wait_group 0;");
    __syncthreads();

    for (int kt = 0; kt < KT; kt++) {
        int cur = kt & 1;
        if (kt + 1 < KT)
            load_stage(smem + (cur ^ 1) * 4 * GTILE, Ah, Al, Bh, Bl,
                       tid, m0, n0, K, (kt + 1) * 32);

        const __nv_bfloat16* sAh = smem + cur * 4 * GTILE;
        const __nv_bfloat16* sAl = sAh + GTILE;
        const __nv_bfloat16* sBh = sAh + 2 * GTILE;
        const __nv_bfloat16* sBl = sAh + 3 * GTILE;

#pragma unroll
        for (int kk = 0; kk < 32; kk += 16) {
            u32 ah[4][4], al[4][4], bh[4][2], bl[4][2];
            int arow = wm * 64 + (lane & 7) + ((lane >> 3) & 1) * 8;
            int acol = kk + ((lane >> 4) & 1) * 8;
#pragma unroll
            for (int mt = 0; mt < 4; mt++) {
                ldsm4(ah[mt][0], ah[mt][1], ah[mt][2], ah[mt][3],
                      sAh + (arow + mt * 16) * GSTR + acol);
                ldsm4(al[mt][0], al[mt][1], al[mt][2], al[mt][3],
                      sAl + (arow + mt * 16) * GSTR + acol);
            }
            int brow = wn * 32 + (lane & 7) + ((lane >> 4) & 1) * 8;
            int bcol = kk + ((lane >> 3) & 1) * 8;
#pragma unroll
            for (int p = 0; p < 2; p++) {
                u32 r0, r1, r2, r3;
                ldsm4(r0, r1, r2, r3, sBh + (brow + p * 16) * GSTR + bcol);
                bh[2 * p][0] = r0; bh[2 * p][1] = r1;
                bh[2 * p + 1][0] = r2; bh[2 * p + 1][1] = r3;
                ldsm4(r0, r1, r2, r3, sBl + (brow + p * 16) * GSTR + bcol);
                bl[2 * p][0] = r0; bl[2 * p][1] = r1;
                bl[2 * p + 1][0] = r2; bl[2 * p + 1][1] = r3;
            }
#pragma unroll
            for (int mt = 0; mt < 4; mt++) {
#pragma unroll
                for (int nt = 0; nt < 4; nt++) {
                    mma16816(acc[mt][nt], ah[mt], bh[nt]);
                    mma16816(acc[mt][nt], ah[mt], bl[nt]);
                    mma16816(acc[mt][nt], al[mt], bh[nt]);
                }
            }
        }
        asm volatile("cp.async.wait_group 0;");
        __syncthreads();
    }

#pragma unroll
    for (int mt = 0; mt < 4; mt++) {
#pragma unroll
        for (int nt = 0; nt < 4; nt++) {
            int r = m0 + wm * 64 + mt * 16 + (lane >> 2);
            int c = n0 + wn * 32 + nt * 8 + (lane & 3) * 2;
            float2 v0 = make_float2(acc[mt][nt][0], acc[mt][nt][1]);
            float2 v1 = make_float2(acc[mt][nt][2], acc[mt][nt][3]);
            *(float2*)&C[(size_t)r * N + c] = v0;
            *(float2*)&C[(size_t)(r + 8) * N + c] = v1;
        }
    }
}

// ---------------------------------------------------------------------------
// RoPE + optional scale + fp16 split: fp32 [B,S,n_heads,HD] -> (hi, lo) fp16
// ---------------------------------------------------------------------------
__global__ void rope_split(const float* __restrict__ t,
                           __half* __restrict__ th, __half* __restrict__ tl,
                           const float* __restrict__ fc,
                           const float* __restrict__ fs,
                           int n_heads, float scale, int total)
{
    int idx = blockIdx.x * blockDim.x + threadIdx.x;
    if (idx >= total) return;
    int p  = idx & 63;
    int h  = (idx >> 6) % n_heads;
    int bs = (idx >> 6) / n_heads;
    int srow = bs % SS;
    size_t off = ((size_t)bs * n_heads + h) * HD + 2 * p;
    float c  = fc[srow * 64 + p];
    float sn = fs[srow * 64 + p];
    float tr = t[off], ti = t[off + 1];
    float r0 = (tr * c - ti * sn) * scale;
    float r1 = (tr * sn + ti * c) * scale;
    __half h0 = __float2half_rn(r0), h1 = __float2half_rn(r1);
    __half l0 = __float2half_rn(r0 - __half2float(h0));
    __half l1 = __float2half_rn(r1 - __half2float(h1));
    *(__half2*)&th[off] = __half2(h0, h1);
    *(__half2*)&tl[off] = __half2(l0, l1);
}

// ---------------------------------------------------------------------------
// fast exp on the FMA pipe (no MUFU): valid for x <= ~0, clamped at -87
// ---------------------------------------------------------------------------
__device__ __forceinline__ float fast_exp(float x) {
    x = fmaxf(x, -87.f);
    float z = x * 1.4426950408889634f;
    float t = z + 12582912.f;              // round-to-nearest int via magic
    int   e = __float_as_int(t) << 23;
    float n = t - 12582912.f;
    float f = z - n;                       // f in [-0.5, 0.5]
    float p = 1.3387706e-3f;
    p = fmaf(p, f, 9.6181291e-3f);
    p = fmaf(p, f, 5.5504108e-2f);
    p = fmaf(p, f, 2.4022650e-1f);
    p = fmaf(p, f, 6.9314718e-1f);
    p = fmaf(p, f, 1.0f);
    return __int_as_float(__float_as_int(p) + e);
}

// ---------------------------------------------------------------------------
// Tensor-core flash attention: fp16-split Q@K^T (3 passes), fp16 P@V.
// BM=BN=64, 4 warps (each owns 16 q rows), 128 threads.
// ---------------------------------------------------------------------------
#define FSTR 136                    // fp16 smem row stride (128 + 8)
#define FA2_TILE (64 * FSTR)
#define FA2_SMEM (5 * FA2_TILE * 2) // 87040 bytes

__global__ __launch_bounds__(128) void flash_mma(
    const __half* __restrict__ qh, const __half* __restrict__ ql,
    const __half* __restrict__ kh, const __half* __restrict__ kl,
    const __half* __restrict__ vv, float* __restrict__ out)
{
    extern __shared__ __half sm2[];
    __half* sqh = sm2;
    __half* sql = sqh + FA2_TILE;
    __half* skh = sql + FA2_TILE;
    __half* skl = skh + FA2_TILE;
    __half* sv  = skl + FA2_TILE;

    int tid = threadIdx.x, lane = tid & 31, wid = tid >> 5;
    int qt = gridDim.x - 1 - blockIdx.x;      // heavy blocks first
    int bh = blockIdx.y;
    int b = bh >> 5, h = bh & 31, kvh = h >> 2;
    int q0 = qt * 64;

    // load Q tile (hi+lo)
#pragma unroll
    for (int i = 0; i < 8; i++) {
        int c = tid + i * 128;
        int row = c >> 4;
        int col = (c & 15) * 8;
        size_t g = ((size_t)(b * SS + q0 + row) * NH + h) * HD + col;
        *(int4*)&sqh[row * FSTR + col] = *(const int4*)&qh[g];
        *(int4*)&sql[row * FSTR + col] = *(const int4*)&ql[g];
    }

    float o[16][4];
#pragma unroll
    for (int n = 0; n < 16; n++)
#pragma unroll
        for (int j = 0; j < 4; j++) o[n][j] = 0.f;
    float m0 = -1e30f, m1 = -1e30f, l0 = 0.f, l1 = 0.f;

    int gr = lane >> 2, qc = (lane & 3) * 2;
    int arow = wid * 16 + (lane & 7) + ((lane >> 3) & 1) * 8;
    int acolo = ((lane >> 4) & 1) * 8;
    int brow = (lane & 7) + ((lane >> 4) & 1) * 8;
    int bcolo = ((lane >> 3) & 1) * 8;
    int vrow = (lane & 7) + ((lane >> 3) & 1) * 8;
    int vcolo = ((lane >> 4) & 1) * 8;

    for (int nt = 0; nt <= qt; nt++) {
        int k0 = nt * 64;
        __syncthreads();
#pragma unroll
        for (int i = 0; i < 8; i++) {
            int c = tid + i * 128;
            int row = c >> 4;
            int col = (c & 15) * 8;
            size_t g = ((size_t)(b * SS + k0 + row) * NKV + kvh) * HD + col;
            *(int4*)&skh[row * FSTR + col] = *(const int4*)&kh[g];
            *(int4*)&skl[row * FSTR + col] = *(const int4*)&kl[g];
            *(int4*)&sv [row * FSTR + col] = *(const int4*)&vv[g];
        }
        __syncthreads();

        // S = Q K^T (hi*hi + hi*lo + lo*hi)
        float s[8][4];
#pragma unroll
        for (int n = 0; n < 8; n++)
#pragma unroll
            for (int j = 0; j < 4; j++) s[n][j] = 0.f;

#pragma unroll
        for (int kc = 0; kc < 8; kc++) {
            u32 aH[4], aL[4];
            ldsm4(aH[0], aH[1], aH[2], aH[3], &sqh[arow * FSTR + kc * 16 + acolo]);
            ldsm4(aL[0], aL[1], aL[2], aL[3], &sql[arow * FSTR + kc * 16 + acolo]);
            u32 bH[8][2], bL[8][2];
#pragma unroll
            for (int p = 0; p < 4; p++) {
                u32 r0, r1, r2, r3;
                ldsm4(r0, r1, r2, r3, &skh[(p * 16 + brow) * FSTR + kc * 16 + bcolo]);
                bH[2 * p][0] = r0; bH[2 * p][1] = r1;
                bH[2 * p + 1][0] = r2; bH[2 * p + 1][1] = r3;
                ldsm4(r0, r1, r2, r3, &skl[(p * 16 + brow) * FSTR + kc * 16 + bcolo]);
                bL[2 * p][0] = r0; bL[2 * p][1] = r1;
                bL[2 * p + 1][0] = r2; bL[2 * p + 1][1] = r3;
            }
#pragma unroll
            for (int n = 0; n < 8; n++) mma16816h(s[n], aH, bH[n]);
#pragma unroll
            for (int n = 0; n < 8; n++) mma16816h(s[n], aH, bL[n]);
#pragma unroll
            for (int n = 0; n < 8; n++) mma16816h(s[n], aL, bH[n]);
        }

        // causal mask on the diagonal tile
        if (nt == qt) {
            int lr0 = wid * 16 + gr, lr1 = lr0 + 8;
#pragma unroll
            for (int n = 0; n < 8; n++) {
                int lc = n * 8 + qc;
                if (lc     > lr0) s[n][0] = -1e30f;
                if (lc + 1 > lr0) s[n][1] = -1e30f;
                if (lc     > lr1) s[n][2] = -1e30f;
                if (lc + 1 > lr1) s[n][3] = -1e30f;
            }
        }

        // online softmax (rows owned by quads)
        float mx0 = -1e30f, mx1 = -1e30f;
#pragma unroll
        for (int n = 0; n < 8; n++) {
            mx0 = fmaxf(mx0, fmaxf(s[n][0], s[n][1]));
            mx1 = fmaxf(mx1, fmaxf(s[n][2], s[n][3]));
        }
        mx0 = fmaxf(mx0, __shfl_xor_sync(0xffffffffu, mx0, 1));
        mx0 = fmaxf(mx0, __shfl_xor_sync(0xffffffffu, mx0, 2));
        mx1 = fmaxf(mx1, __shfl_xor_sync(0xffffffffu, mx1, 1));
        mx1 = fmaxf(mx1, __shfl_xor_sync(0xffffffffu, mx1, 2));
        float nm0 = fmaxf(m0, mx0), nm1 = fmaxf(m1, mx1);
        float a0 = fast_exp(m0 - nm0), a1 = fast_exp(m1 - nm1);
        m0 = nm0; m1 = nm1;

        float ls0 = 0.f, ls1 = 0.f;
        u32 pa[4][4];
#pragma unroll
        for (int n = 0; n < 8; n++) {
            float p0 = fast_exp(s[n][0] - nm0);
            float p1 = fast_exp(s[n][1] - nm0);
            float p2 = fast_exp(s[n][2] - nm1);
            float p3 = fast_exp(s[n][3] - nm1);
            ls0 += p0 + p1; ls1 += p2 + p3;
            __half2 hi = __floats2half2_rn(p0, p1);
            __half2 lo = __floats2half2_rn(p2, p3);
            int j = n >> 1;
            if ((n & 1) == 0) {
                pa[j][0] = *(u32*)&hi; pa[j][1] = *(u32*)&lo;
            } else {
                pa[j][2] = *(u32*)&hi; pa[j][3] = *(u32*)&lo;
            }
        }
        ls0 += __shfl_xor_sync(0xffffffffu, ls0, 1);
        ls0 += __shfl_xor_sync(0xffffffffu, ls0, 2);
        ls1 += __shfl_xor_sync(0xffffffffu, ls1, 1);
        ls1 += __shfl_xor_sync(0xffffffffu, ls1, 2);
        l0 = l0 * a0 + ls0;
        l1 = l1 * a1 + ls1;

#pragma unroll
        for (int n = 0; n < 16; n++) {
            o[n][0] *= a0; o[n][1] *= a0;
            o[n][2] *= a1; o[n][3] *= a1;
        }

        // O += P V  (V row-major [token][d], B-frags via ldmatrix.trans)
#pragma unroll
        for (int np = 0; np < 8; np++) {
#pragma unroll
            for (int j = 0; j < 4; j++) {
                u32 r0, r1, r2, r3;
                ldsm4t(r0, r1, r2, r3, &sv[(j * 16 + vrow) * FSTR + np * 16 + vcolo]);
                u32 bv0[2] = {r0, r1};
                u32 bv1[2] = {r2, r3};
                mma16816h(o[2 * np],     pa[j], bv0);
                mma16816h(o[2 * np + 1], pa[j], bv1);
            }
        }
    }

    // finalize
    float inv0 = 1.f / l0, inv1 = 1.f / l1;
    int row0 = q0 + wid * 16 + gr;
#pragma unroll
    for (int n = 0; n < 16; n++) {
        int col = n * 8 + qc;
        size_t base0 = ((size_t)(b * SS + row0)     * NH + h) * HD + col;
        size_t base1 = ((size_t)(b * SS + row0 + 8) * NH + h) * HD + col;
        *(float2*)&out[base0] = make_float2(o[n][0] * inv0, o[n][1] * inv0);
        *(float2*)&out[base1] = make_float2(o[n][2] * inv1, o[n][3] * inv1);
    }
}

// ---------------------------------------------------------------------------
extern "C" void kernel_launch(void* const* d_in, const int* in_sizes, int n_in,
                              void* d_out, int out_size)
{
    const float* x   = (const float*)d_in[0];
    const float* wq  = (const float*)d_in[1];
    const float* wk  = (const float*)d_in[2];
    const float* wv  = (const float*)d_in[3];
    const float* wo  = (const float*)d_in[4];
    const float* fc  = (const float*)d_in[5];
    const float* fs  = (const float*)d_in[6];
    float* out = (float*)d_out;

    float *xq, *xk, *xv, *at;
    cudaGetSymbolAddress((void**)&xq, g_xq);
    cudaGetSymbolAddress((void**)&xk, g_xk);
    cudaGetSymbolAddress((void**)&xv, g_xv);
    cudaGetSymbolAddress((void**)&at, g_attn);
    __nv_bfloat16 *xh, *xl, *wqh, *wql, *wkh, *wkl, *wvh, *wvl, *woh, *wol, *ah, *al;
    cudaGetSymbolAddress((void**)&xh, g_xh);   cudaGetSymbolAddress((void**)&xl, g_xl);
    cudaGetSymbolAddress((void**)&wqh, g_wqh); cudaGetSymbolAddress((void**)&wql, g_wql);
    cudaGetSymbolAddress((void**)&wkh, g_wkh); cudaGetSymbolAddress((void**)&wkl, g_wkl);
    cudaGetSymbolAddress((void**)&wvh, g_wvh); cudaGetSymbolAddress((void**)&wvl, g_wvl);
    cudaGetSymbolAddress((void**)&woh, g_woh); cudaGetSymbolAddress((void**)&wol, g_wol);
    cudaGetSymbolAddress((void**)&ah, g_ah);   cudaGetSymbolAddress((void**)&al, g_al);
    __half *qhp, *qlp, *khp, *klp, *vhp;
    cudaGetSymbolAddress((void**)&qhp, g_qh);  cudaGetSymbolAddress((void**)&qlp, g_ql);
    cudaGetSymbolAddress((void**)&khp, g_kh);  cudaGetSymbolAddress((void**)&klp, g_kl);
    cudaGetSymbolAddress((void**)&vhp, g_vh);

    const int GEMM_SMEM = 2 * 4 * GTILE * (int)sizeof(__nv_bfloat16);
    cudaFuncSetAttribute(gemm_bf16x2, cudaFuncAttributeMaxDynamicSharedMemorySize, GEMM_SMEM);
    cudaFuncSetAttribute(flash_mma, cudaFuncAttributeMaxDynamicSharedMemorySize, FA2_SMEM);

    // input splits (bf16 for GEMM)
    int nx  = M_TOK * DIM, nw = DIM * DIM, nkv = KVDIM * DIM;
    split_kernel<<<nx / 4 / 256, 256>>>(x, xh, xl, nx);
    split_kernel<<<nw / 4 / 256, 256>>>(wq, wqh, wql, nw);
    split_kernel<<<nkv / 4 / 256, 256>>>(wk, wkh, wkl, nkv);
    split_kernel<<<nkv / 4 / 256, 256>>>(wv, wvh, wvl, nkv);
    split_kernel<<<nw / 4 / 256, 256>>>(wo, woh, wol, nw);

    // projections
    dim3 gq(DIM / 128, M_TOK / 128);
    dim3 gkv(KVDIM / 128, M_TOK / 128);
    gemm_bf16x2<<<gq, 256, GEMM_SMEM>>>(xh, xl, wqh, wql, xq, M_TOK, DIM, DIM);
    gemm_bf16x2<<<gkv, 256, GEMM_SMEM>>>(xh, xl, wkh, wkl, xk, M_TOK, KVDIM, DIM);
    gemm_bf16x2<<<gkv, 256, GEMM_SMEM>>>(xh, xl, wvh, wvl, xv, M_TOK, KVDIM, DIM);

    // RoPE + fp16 split (softmax scale folded into q)
    const float scale = 0.08838834764831845f;  // 1/sqrt(128)
    int totq = BB * SS * NH  * (HD / 2);
    int totk = BB * SS * NKV * (HD / 2);
    rope_split<<<(totq + 255) / 256, 256>>>(xq, qhp, qlp, fc, fs, NH,  scale, totq);
    rope_split<<<(totk + 255) / 256, 256>>>(xk, khp, klp, fc, fs, NKV, 1.0f,  totk);
    int nv = M_TOK * KVDIM;
    split_half<<<nv / 4 / 256, 256>>>(xv, vhp, nv);

    // tensor-core flash attention
    dim3 ga(SS / 64, BB * NH);
    flash_mma<<<ga, 128, FA2_SMEM>>>(qhp, qlp, khp, klp, vhp, at);

    // output projection
    split_kernel<<<nx / 4 / 256, 256>>>(at, ah, al, nx);
    gemm_bf16x2<<<gq, 256, GEMM_SMEM>>>(ah, al, woh, wol, out, M_TOK, DIM, DIM);
}

// round 7
// speedup vs baseline: 4.5913x; 1.5503x over previous
#include <cuda_runtime.h>
#include <cuda_bf16.h>
#include <cuda_fp16.h>
#include <cstdint>
#include <cstddef>
#include <math.h>
#include <float.h>

typedef unsigned int u32;

#define BB 2
#define SS 2048
#define DIM 4096
#define NH 32
#define NKV 8
#define HD 128
#define NREP 4
#define M_TOK (BB*SS)
#define KVDIM (NKV*HD)

// ---------------- scratch (allocation-free device globals) ----------------
__device__ float g_xq[(size_t)M_TOK * DIM];
__device__ float g_xk[(size_t)M_TOK * KVDIM];
__device__ float g_xv[(size_t)M_TOK * KVDIM];
__device__ float g_attn[(size_t)M_TOK * DIM];

// fp16 GEMM operands: A-side split hi/lo, B-side (weights) single fp16
__device__ __half g_xh[(size_t)M_TOK * DIM],  g_xl[(size_t)M_TOK * DIM];
__device__ __half g_ah[(size_t)M_TOK * DIM],  g_al[(size_t)M_TOK * DIM];
__device__ __half g_wq[(size_t)DIM * DIM],   g_wo[(size_t)DIM * DIM];
__device__ __half g_wk[(size_t)KVDIM * DIM], g_wv[(size_t)KVDIM * DIM];

// fp16 attention operands
__device__ __half g_qh[(size_t)M_TOK * DIM],   g_ql[(size_t)M_TOK * DIM];
__device__ __half g_kh[(size_t)M_TOK * KVDIM], g_kl[(size_t)M_TOK * KVDIM];
__device__ __half g_vh[(size_t)M_TOK * KVDIM];

// ---------------------------------------------------------------------------
// fp32 -> (fp16 hi, fp16 lo)
// ---------------------------------------------------------------------------
__global__ void split2h(const float* __restrict__ in,
                        __half* __restrict__ hi, __half* __restrict__ lo, int n)
{
    int i = (blockIdx.x * blockDim.x + threadIdx.x) * 4;
    if (i >= n) return;
    float4 v = *(const float4*)&in[i];
    float f[4] = {v.x, v.y, v.z, v.w};
    __half h[4], l[4];
#pragma unroll
    for (int k = 0; k < 4; k++) {
        h[k] = __float2half_rn(f[k]);
        l[k] = __float2half_rn(f[k] - __half2float(h[k]));
    }
    *(__half2*)&hi[i]     = __half2(h[0], h[1]);
    *(__half2*)&hi[i + 2] = __half2(h[2], h[3]);
    *(__half2*)&lo[i]     = __half2(l[0], l[1]);
    *(__half2*)&lo[i + 2] = __half2(l[2], l[3]);
}

// fp32 -> fp16
__global__ void split_half(const float* __restrict__ in, __half* __restrict__ out, int n)
{
    int i = (blockIdx.x * blockDim.x + threadIdx.x) * 4;
    if (i >= n) return;
    float4 v = *(const float4*)&in[i];
    *(__half2*)&out[i]     = __floats2half2_rn(v.x, v.y);
    *(__half2*)&out[i + 2] = __floats2half2_rn(v.z, v.w);
}

// ---------------------------------------------------------------------------
// common PTX helpers
// ---------------------------------------------------------------------------
__device__ __forceinline__ void cpasync16(const void* s, const void* g) {
    u32 sa = (u32)__cvta_generic_to_shared(s);
    asm volatile("cp.async.cg.shared.global [%0], [%1], 16;\n" :: "r"(sa), "l"(g));
}
__device__ __forceinline__ void ldsm4(u32& r0, u32& r1, u32& r2,
                                      u32& r3, const void* p) {
    u32 a = (u32)__cvta_generic_to_shared(p);
    asm volatile("ldmatrix.sync.aligned.m8n8.x4.shared.b16 {%0,%1,%2,%3}, [%4];"
                 : "=r"(r0), "=r"(r1), "=r"(r2), "=r"(r3) : "r"(a));
}
__device__ __forceinline__ void ldsm4t(u32& r0, u32& r1, u32& r2,
                                       u32& r3, const void* p) {
    u32 a = (u32)__cvta_generic_to_shared(p);
    asm volatile("ldmatrix.sync.aligned.m8n8.x4.trans.shared.b16 {%0,%1,%2,%3}, [%4];"
                 : "=r"(r0), "=r"(r1), "=r"(r2), "=r"(r3) : "r"(a));
}
__device__ __forceinline__ void mma16816h(float* c, const u32* a, const u32* b) {
    asm volatile(
        "mma.sync.aligned.m16n8k16.row.col.f32.f16.f16.f32 "
        "{%0,%1,%2,%3}, {%4,%5,%6,%7}, {%8,%9}, {%0,%1,%2,%3};"
        : "+f"(c[0]), "+f"(c[1]), "+f"(c[2]), "+f"(c[3])
        : "r"(a[0]), "r"(a[1]), "r"(a[2]), "r"(a[3]), "r"(b[0]), "r"(b[1]));
}

// ---------------------------------------------------------------------------
// fp16x2 split GEMM (NT): C[m][n] = sum_k A[m][k]*B[n][k], fp32 out.
// C = Ah*B + Al*B (2 tensor passes). Block 128x128x32, 8 warps, warp 64x32.
// ---------------------------------------------------------------------------
#define GSTR 40
#define GTILE (128*GSTR)
#define GEMM_SMEM (2 * 3 * GTILE * 2)   // 61440 bytes

__device__ __forceinline__ void load_stage(
    __half* sb,
    const __half* __restrict__ Ah, const __half* __restrict__ Al,
    const __half* __restrict__ Bm,
    int tid, int m0, int n0, int K, int k0)
{
#pragma unroll
    for (int i = 0; i < 2; i++) {
        int c = tid + i * 256;
        int row = c >> 2;
        int col = (c & 3) * 8;
        size_t ga = (size_t)(m0 + row) * K + k0 + col;
        size_t gb = (size_t)(n0 + row) * K + k0 + col;
        cpasync16(&sb[0 * GTILE + row * GSTR + col], &Ah[ga]);
        cpasync16(&sb[1 * GTILE + row * GSTR + col], &Al[ga]);
        cpasync16(&sb[2 * GTILE + row * GSTR + col], &Bm[gb]);
    }
    asm volatile("cp.async.commit_group;");
}

__global__ __launch_bounds__(256, 2) void gemm_f16x2(
    const __half* __restrict__ Ah, const __half* __restrict__ Al,
    const __half* __restrict__ Bm,
    float* __restrict__ C, int M, int N, int K)
{
    extern __shared__ __half smem[];
    int tid = threadIdx.x;
    int lane = tid & 31, wid = tid >> 5;
    int wm = wid & 1, wn = wid >> 1;
    int m0 = blockIdx.y * 128, n0 = blockIdx.x * 128;

    float acc[4][4][4];
#pragma unroll
    for (int i = 0; i < 4; i++)
#pragma unroll
        for (int j = 0; j < 4; j++)
#pragma unroll
            for (int k = 0; k < 4; k++) acc[i][j][k] = 0.f;

    const int KT = K / 32;

    load_stage(smem, Ah, Al, Bm, tid, m0, n0, K, 0);
    asm volatile("cp.async.wait_group 0;");
    __syncthreads();

    for (int kt = 0; kt < KT; kt++) {
        int cur = kt & 1;
        if (kt + 1 < KT)
            load_stage(smem + (cur ^ 1) * 3 * GTILE, Ah, Al, Bm,
                       tid, m0, n0, K, (kt + 1) * 32);

        const __half* sAh = smem + cur * 3 * GTILE;
        const __half* sAl = sAh + GTILE;
        const __half* sB  = sAh + 2 * GTILE;

#pragma unroll
        for (int kk = 0; kk < 32; kk += 16) {
            u32 ah[4][4], al[4][4], bb[4][2];
            int arow = wm * 64 + (lane & 7) + ((lane >> 3) & 1) * 8;
            int acol = kk + ((lane >> 4) & 1) * 8;
#pragma unroll
            for (int mt = 0; mt < 4; mt++) {
                ldsm4(ah[mt][0], ah[mt][1], ah[mt][2], ah[mt][3],
                      sAh + (arow + mt * 16) * GSTR + acol);
                ldsm4(al[mt][0], al[mt][1], al[mt][2], al[mt][3],
                      sAl + (arow + mt * 16) * GSTR + acol);
            }
            int brow = wn * 32 + (lane & 7) + ((lane >> 4) & 1) * 8;
            int bcol = kk + ((lane >> 3) & 1) * 8;
#pragma unroll
            for (int p = 0; p < 2; p++) {
                u32 r0, r1, r2, r3;
                ldsm4(r0, r1, r2, r3, sB + (brow + p * 16) * GSTR + bcol);
                bb[2 * p][0] = r0; bb[2 * p][1] = r1;
                bb[2 * p + 1][0] = r2; bb[2 * p + 1][1] = r3;
            }
#pragma unroll
            for (int mt = 0; mt < 4; mt++) {
#pragma unroll
                for (int nt = 0; nt < 4; nt++) {
                    mma16816h(acc[mt][nt], ah[mt], bb[nt]);
                    mma16816h(acc[mt][nt], al[mt], bb[nt]);
                }
            }
        }
        asm volatile("cp.async.wait_group 0;");
        __syncthreads();
    }

#pragma unroll
    for (int mt = 0; mt < 4; mt++) {
#pragma unroll
        for (int nt = 0; nt < 4; nt++) {
            int r = m0 + wm * 64 + mt * 16 + (lane >> 2);
            int c = n0 + wn * 32 + nt * 8 + (lane & 3) * 2;
            float2 v0 = make_float2(acc[mt][nt][0], acc[mt][nt][1]);
            float2 v1 = make_float2(acc[mt][nt][2], acc[mt][nt][3]);
            *(float2*)&C[(size_t)r * N + c] = v0;
            *(float2*)&C[(size_t)(r + 8) * N + c] = v1;
        }
    }
}

// ---------------------------------------------------------------------------
// RoPE + optional scale + fp16 split
// ---------------------------------------------------------------------------
__global__ void rope_split(const float* __restrict__ t,
                           __half* __restrict__ th, __half* __restrict__ tl,
                           const float* __restrict__ fc,
                           const float* __restrict__ fs,
                           int n_heads, float scale, int total)
{
    int idx = blockIdx.x * blockDim.x + threadIdx.x;
    if (idx >= total) return;
    int p  = idx & 63;
    int h  = (idx >> 6) % n_heads;
    int bs = (idx >> 6) / n_heads;
    int srow = bs % SS;
    size_t off = ((size_t)bs * n_heads + h) * HD + 2 * p;
    float c  = fc[srow * 64 + p];
    float sn = fs[srow * 64 + p];
    float tr = t[off], ti = t[off + 1];
    float r0 = (tr * c - ti * sn) * scale;
    float r1 = (tr * sn + ti * c) * scale;
    __half h0 = __float2half_rn(r0), h1 = __float2half_rn(r1);
    __half l0 = __float2half_rn(r0 - __half2float(h0));
    __half l1 = __float2half_rn(r1 - __half2float(h1));
    *(__half2*)&th[off] = __half2(h0, h1);
    *(__half2*)&tl[off] = __half2(l0, l1);
}

// ---------------------------------------------------------------------------
// fast exp on the FMA pipe
// ---------------------------------------------------------------------------
__device__ __forceinline__ float fast_exp(float x) {
    x = fmaxf(x, -87.f);
    float z = x * 1.4426950408889634f;
    float t = z + 12582912.f;
    int   e = __float_as_int(t) << 23;
    float n = t - 12582912.f;
    float f = z - n;
    float p = 1.3387706e-3f;
    p = fmaf(p, f, 9.6181291e-3f);
    p = fmaf(p, f, 5.5504108e-2f);
    p = fmaf(p, f, 2.4022650e-1f);
    p = fmaf(p, f, 6.9314718e-1f);
    p = fmaf(p, f, 1.0f);
    return __int_as_float(__float_as_int(p) + e);
}

// ---------------------------------------------------------------------------
// Tensor-core flash attention (mma.sync), unchanged from round 5 (passing).
// ---------------------------------------------------------------------------
#define FSTR 136
#define FA2_TILE (64 * FSTR)
#define FA2_SMEM (5 * FA2_TILE * 2)

__global__ __launch_bounds__(128) void flash_mma(
    const __half* __restrict__ qh, const __half* __restrict__ ql,
    const __half* __restrict__ kh, const __half* __restrict__ kl,
    const __half* __restrict__ vv, float* __restrict__ out)
{
    extern __shared__ __half sm2[];
    __half* sqh = sm2;
    __half* sql = sqh + FA2_TILE;
    __half* skh = sql + FA2_TILE;
    __half* skl = skh + FA2_TILE;
    __half* sv  = skl + FA2_TILE;

    int tid = threadIdx.x, lane = tid & 31, wid = tid >> 5;
    int qt = gridDim.x - 1 - blockIdx.x;
    int bh = blockIdx.y;
    int b = bh >> 5, h = bh & 31, kvh = h >> 2;
    int q0 = qt * 64;

#pragma unroll
    for (int i = 0; i < 8; i++) {
        int c = tid + i * 128;
        int row = c >> 4;
        int col = (c & 15) * 8;
        size_t g = ((size_t)(b * SS + q0 + row) * NH + h) * HD + col;
        *(int4*)&sqh[row * FSTR + col] = *(const int4*)&qh[g];
        *(int4*)&sql[row * FSTR + col] = *(const int4*)&ql[g];
    }

    float o[16][4];
#pragma unroll
    for (int n = 0; n < 16; n++)
#pragma unroll
        for (int j = 0; j < 4; j++) o[n][j] = 0.f;
    float m0 = -1e30f, m1 = -1e30f, l0 = 0.f, l1 = 0.f;

    int gr = lane >> 2, qc = (lane & 3) * 2;
    int arow = wid * 16 + (lane & 7) + ((lane >> 3) & 1) * 8;
    int acolo = ((lane >> 4) & 1) * 8;
    int brow = (lane & 7) + ((lane >> 4) & 1) * 8;
    int bcolo = ((lane >> 3) & 1) * 8;
    int vrow = (lane & 7) + ((lane >> 3) & 1) * 8;
    int vcolo = ((lane >> 4) & 1) * 8;

    for (int nt = 0; nt <= qt; nt++) {
        int k0 = nt * 64;
        __syncthreads();
#pragma unroll
        for (int i = 0; i < 8; i++) {
            int c = tid + i * 128;
            int row = c >> 4;
            int col = (c & 15) * 8;
            size_t g = ((size_t)(b * SS + k0 + row) * NKV + kvh) * HD + col;
            *(int4*)&skh[row * FSTR + col] = *(const int4*)&kh[g];
            *(int4*)&skl[row * FSTR + col] = *(const int4*)&kl[g];
            *(int4*)&sv [row * FSTR + col] = *(const int4*)&vv[g];
        }
        __syncthreads();

        float s[8][4];
#pragma unroll
        for (int n = 0; n < 8; n++)
#pragma unroll
            for (int j = 0; j < 4; j++) s[n][j] = 0.f;

#pragma unroll
        for (int kc = 0; kc < 8; kc++) {
            u32 aH[4], aL[4];
            ldsm4(aH[0], aH[1], aH[2], aH[3], &sqh[arow * FSTR + kc * 16 + acolo]);
            ldsm4(aL[0], aL[1], aL[2], aL[3], &sql[arow * FSTR + kc * 16 + acolo]);
            u32 bH[8][2], bL[8][2];
#pragma unroll
            for (int p = 0; p < 4; p++) {
                u32 r0, r1, r2, r3;
                ldsm4(r0, r1, r2, r3, &skh[(p * 16 + brow) * FSTR + kc * 16 + bcolo]);
                bH[2 * p][0] = r0; bH[2 * p][1] = r1;
                bH[2 * p + 1][0] = r2; bH[2 * p + 1][1] = r3;
                ldsm4(r0, r1, r2, r3, &skl[(p * 16 + brow) * FSTR + kc * 16 + bcolo]);
                bL[2 * p][0] = r0; bL[2 * p][1] = r1;
                bL[2 * p + 1][0] = r2; bL[2 * p + 1][1] = r3;
            }
#pragma unroll
            for (int n = 0; n < 8; n++) mma16816h(s[n], aH, bH[n]);
#pragma unroll
            for (int n = 0; n < 8; n++) mma16816h(s[n], aH, bL[n]);
#pragma unroll
            for (int n = 0; n < 8; n++) mma16816h(s[n], aL, bH[n]);
        }

        if (nt == qt) {
            int lr0 = wid * 16 + gr, lr1 = lr0 + 8;
#pragma unroll
            for (int n = 0; n < 8; n++) {
                int lc = n * 8 + qc;
                if (lc     > lr0) s[n][0] = -1e30f;
                if (lc + 1 > lr0) s[n][1] = -1e30f;
                if (lc     > lr1) s[n][2] = -1e30f;
                if (lc + 1 > lr1) s[n][3] = -1e30f;
            }
        }

        float mx0 = -1e30f, mx1 = -1e30f;
#pragma unroll
        for (int n = 0; n < 8; n++) {
            mx0 = fmaxf(mx0, fmaxf(s[n][0], s[n][1]));
            mx1 = fmaxf(mx1, fmaxf(s[n][2], s[n][3]));
        }
        mx0 = fmaxf(mx0, __shfl_xor_sync(0xffffffffu, mx0, 1));
        mx0 = fmaxf(mx0, __shfl_xor_sync(0xffffffffu, mx0, 2));
        mx1 = fmaxf(mx1, __shfl_xor_sync(0xffffffffu, mx1, 1));
        mx1 = fmaxf(mx1, __shfl_xor_sync(0xffffffffu, mx1, 2));
        float nm0 = fmaxf(m0, mx0), nm1 = fmaxf(m1, mx1);
        float a0 = fast_exp(m0 - nm0), a1 = fast_exp(m1 - nm1);
        m0 = nm0; m1 = nm1;

        float ls0 = 0.f, ls1 = 0.f;
        u32 pa[4][4];
#pragma unroll
        for (int n = 0; n < 8; n++) {
            float p0 = fast_exp(s[n][0] - nm0);
            float p1 = fast_exp(s[n][1] - nm0);
            float p2 = fast_exp(s[n][2] - nm1);
            float p3 = fast_exp(s[n][3] - nm1);
            ls0 += p0 + p1; ls1 += p2 + p3;
            __half2 hi = __floats2half2_rn(p0, p1);
            __half2 lo = __floats2half2_rn(p2, p3);
            int j = n >> 1;
            if ((n & 1) == 0) {
                pa[j][0] = *(u32*)&hi; pa[j][1] = *(u32*)&lo;
            } else {
                pa[j][2] = *(u32*)&hi; pa[j][3] = *(u32*)&lo;
            }
        }
        ls0 += __shfl_xor_sync(0xffffffffu, ls0, 1);
        ls0 += __shfl_xor_sync(0xffffffffu, ls0, 2);
        ls1 += __shfl_xor_sync(0xffffffffu, ls1, 1);
        ls1 += __shfl_xor_sync(0xffffffffu, ls1, 2);
        l0 = l0 * a0 + ls0;
        l1 = l1 * a1 + ls1;

#pragma unroll
        for (int n = 0; n < 16; n++) {
            o[n][0] *= a0; o[n][1] *= a0;
            o[n][2] *= a1; o[n][3] *= a1;
        }

#pragma unroll
        for (int np = 0; np < 8; np++) {
#pragma unroll
            for (int j = 0; j < 4; j++) {
                u32 r0, r1, r2, r3;
                ldsm4t(r0, r1, r2, r3, &sv[(j * 16 + vrow) * FSTR + np * 16 + vcolo]);
                u32 bv0[2] = {r0, r1};
                u32 bv1[2] = {r2, r3};
                mma16816h(o[2 * np],     pa[j], bv0);
                mma16816h(o[2 * np + 1], pa[j], bv1);
            }
        }
    }

    float inv0 = 1.f / l0, inv1 = 1.f / l1;
    int row0 = q0 + wid * 16 + gr;
#pragma unroll
    for (int n = 0; n < 16; n++) {
        int col = n * 8 + qc;
        size_t base0 = ((size_t)(b * SS + row0)     * NH + h) * HD + col;
        size_t base1 = ((size_t)(b * SS + row0 + 8) * NH + h) * HD + col;
        *(float2*)&out[base0] = make_float2(o[n][0] * inv0, o[n][1] * inv0);
        *(float2*)&out[base1] = make_float2(o[n][2] * inv1, o[n][3] * inv1);
    }
}

// ---------------------------------------------------------------------------
extern "C" void kernel_launch(void* const* d_in, const int* in_sizes, int n_in,
                              void* d_out, int out_size)
{
    const float* x   = (const float*)d_in[0];
    const float* wq  = (const float*)d_in[1];
    const float* wk  = (const float*)d_in[2];
    const float* wv  = (const float*)d_in[3];
    const float* wo  = (const float*)d_in[4];
    const float* fc  = (const float*)d_in[5];
    const float* fs  = (const float*)d_in[6];
    float* out = (float*)d_out;

    float *xq, *xk, *xv, *at;
    cudaGetSymbolAddress((void**)&xq, g_xq);
    cudaGetSymbolAddress((void**)&xk, g_xk);
    cudaGetSymbolAddress((void**)&xv, g_xv);
    cudaGetSymbolAddress((void**)&at, g_attn);
    __half *xh, *xl, *ah, *al, *wqf, *wkf, *wvf, *wof;
    cudaGetSymbolAddress((void**)&xh, g_xh);   cudaGetSymbolAddress((void**)&xl, g_xl);
    cudaGetSymbolAddress((void**)&ah, g_ah);   cudaGetSymbolAddress((void**)&al, g_al);
    cudaGetSymbolAddress((void**)&wqf, g_wq);  cudaGetSymbolAddress((void**)&wkf, g_wk);
    cudaGetSymbolAddress((void**)&wvf, g_wv);  cudaGetSymbolAddress((void**)&wof, g_wo);
    __half *qhp, *qlp, *khp, *klp, *vhp;
    cudaGetSymbolAddress((void**)&qhp, g_qh);  cudaGetSymbolAddress((void**)&qlp, g_ql);
    cudaGetSymbolAddress((void**)&khp, g_kh);  cudaGetSymbolAddress((void**)&klp, g_kl);
    cudaGetSymbolAddress((void**)&vhp, g_vh);

    cudaFuncSetAttribute(gemm_f16x2, cudaFuncAttributeMaxDynamicSharedMemorySize, GEMM_SMEM);
    cudaFuncSetAttribute(flash_mma, cudaFuncAttributeMaxDynamicSharedMemorySize, FA2_SMEM);

    // operand prep
    int nx  = M_TOK * DIM, nw = DIM * DIM, nkv = KVDIM * DIM;
    split2h<<<nx / 4 / 256, 256>>>(x, xh, xl, nx);
    split_half<<<nw / 4 / 256, 256>>>(wq, wqf, nw);
    split_half<<<nkv / 4 / 256, 256>>>(wk, wkf, nkv);
    split_half<<<nkv / 4 / 256, 256>>>(wv, wvf, nkv);
    split_half<<<nw / 4 / 256, 256>>>(wo, wof, nw);

    // projections (2-pass fp16 split on tensor pipe)
    dim3 gq(DIM / 128, M_TOK / 128);
    dim3 gkv(KVDIM / 128, M_TOK / 128);
    gemm_f16x2<<<gq, 256, GEMM_SMEM>>>(xh, xl, wqf, xq, M_TOK, DIM, DIM);
    gemm_f16x2<<<gkv, 256, GEMM_SMEM>>>(xh, xl, wkf, xk, M_TOK, KVDIM, DIM);
    gemm_f16x2<<<gkv, 256, GEMM_SMEM>>>(xh, xl, wvf, xv, M_TOK, KVDIM, DIM);

    // RoPE + fp16 split (softmax scale folded into q)
    const float scale = 0.08838834764831845f;
    int totq = BB * SS * NH  * (HD / 2);
    int totk = BB * SS * NKV * (HD / 2);
    rope_split<<<(totq + 255) / 256, 256>>>(xq, qhp, qlp, fc, fs, NH,  scale, totq);
    rope_split<<<(totk + 255) / 256, 256>>>(xk, khp, klp, fc, fs, NKV, 1.0f,  totk);
    int nv = M_TOK * KVDIM;
    split_half<<<nv / 4 / 256, 256>>>(xv, vhp, nv);

    // attention
    dim3 ga(SS / 64, BB * NH);
    flash_mma<<<ga, 128, FA2_SMEM>>>(qhp, qlp, khp, klp, vhp, at);

    // output projection
    split2h<<<nx / 4 / 256, 256>>>(at, ah, al, nx);
    gemm_f16x2<<<gq, 256, GEMM_SMEM>>>(ah, al, wof, out, M_TOK, DIM, DIM);
}